// round 1
// baseline (speedup 1.0000x reference)
#include <cuda_runtime.h>
#include <cuda_bf16.h>

#define BB 16
#define HH 320
#define WW 320
#define NPIX (BB*HH*WW)       // 1,638,400
#define BIGF 1e12f

// Scratch: row-pass squared distances. [tensor][class][b][y][x]
// class 0 = EDT(mask)  (seed = background, val<=0.5)
// class 1 = EDT(~mask) (seed = foreground, val>0.5)
__device__ float g_row[2][2][BB][HH][WW];
__device__ int    g_flags[2][BB];    // has foreground per (tensor, batch)
__device__ double g_accum;

// ---------------------------------------------------------------------------
// K0: zero flags + accumulator (fresh every launch; graph-capturable)
// ---------------------------------------------------------------------------
__global__ void k_zero() {
    int t = threadIdx.x;
    if (t < 2 * BB) ((int*)g_flags)[t] = 0;
    if (t == 0) g_accum = 0.0;
}

// ---------------------------------------------------------------------------
// K1: row pass. One block per (tensor, b, y). 320 threads.
// Nearest-seed 1D distance via outward search with early exit (binary seeds).
// Exact: first hit at distance d IS the minimum.
// ---------------------------------------------------------------------------
__global__ void __launch_bounds__(WW) k_rowpass(const float* __restrict__ pred,
                                               const float* __restrict__ target) {
    int blk = blockIdx.x;                 // t*BB*HH + b*HH + y
    int t   = blk / (BB * HH);
    int rem = blk % (BB * HH);
    int b   = rem / HH;
    int y   = rem % HH;
    const float* src = t ? target : pred;

    __shared__ unsigned char m[WW];
    __shared__ int anyfg;

    int x = threadIdx.x;
    float v = src[(b * HH + y) * WW + x];
    unsigned char bit = (v > 0.5f) ? 1 : 0;
    m[x] = bit;
    if (x == 0) anyfg = 0;
    __syncthreads();

    unsigned ball = __ballot_sync(0xffffffffu, bit != 0);
    if ((x & 31) == 0 && ball) atomicOr(&anyfg, 1);

    // outward search for both seed classes
    int dA = bit ? -1 : 0;   // seed for class 0 = !mask
    int dB = bit ? 0 : -1;   // seed for class 1 = mask
    for (int d = 1; d < WW; ++d) {
        if (dA >= 0 && dB >= 0) break;
        int jm = x - d, jp = x + d;
        unsigned char bm = (jm >= 0) ? m[jm] : 0xAA;   // 0xAA = invalid
        unsigned char bp = (jp < WW) ? m[jp] : 0xAA;
        if (dA < 0 && (bm == 0 || bp == 0)) dA = d;
        if (dB < 0 && (bm == 1 || bp == 1)) dB = d;
    }
    float gA = (dA >= 0) ? (float)(dA * dA) : BIGF;
    float gB = (dB >= 0) ? (float)(dB * dB) : BIGF;
    g_row[t][0][b][y][x] = gA;
    g_row[t][1][b][y][x] = gB;

    __syncthreads();
    if (x == 0 && anyfg) atomicOr(&g_flags[t][b], 1);
}

// ---------------------------------------------------------------------------
// Bounded exact column min-plus: result = min_j col[j] + (i-j)^2, clamped BIG.
// Early exit when d^2 >= current upper bound (all remaining j can't improve).
// ---------------------------------------------------------------------------
__device__ __forceinline__ float colmin(const float* __restrict__ base, int i, int x) {
    float ub = base[i * WW + x];
    #pragma unroll 1
    for (int d = 1; d < HH; ++d) {
        float dd = (float)(d * d);
        if (dd >= ub) break;
        int jm = i - d, jp = i + d;
        if (jm >= 0) ub = fminf(ub, base[jm * WW + x] + dd);
        if (jp < HH) ub = fminf(ub, base[jp * WW + x] + dd);
    }
    return fminf(ub, BIGF);
}

// ---------------------------------------------------------------------------
// K2: column pass + loss + block reduction.
// One thread per pixel (b, i, x); 4 searches (pred/target x bg/fg class).
// ---------------------------------------------------------------------------
__global__ void __launch_bounds__(256) k_loss(const float* __restrict__ pred,
                                              const float* __restrict__ target) {
    int pix = blockIdx.x * blockDim.x + threadIdx.x;
    float term = 0.0f;
    if (pix < NPIX) {
        int b = pix / (HH * WW);
        int r = pix % (HH * WW);
        int i = r / WW;
        int x = r % WW;

        const float* p00 = &g_row[0][0][b][0][0];
        const float* p01 = &g_row[0][1][b][0][0];
        const float* p10 = &g_row[1][0][b][0][0];
        const float* p11 = &g_row[1][1][b][0][0];

        float sqP = colmin(p00, i, x) + colmin(p01, i, x);
        float sqT = colmin(p10, i, x) + colmin(p11, i, x);

        float fP = g_flags[0][b] ? 1.0f : 0.0f;
        float fT = g_flags[1][b] ? 1.0f : 0.0f;

        float pv = pred[pix];
        float tv = target[pix];
        float dv = pv - tv;
        term = dv * dv * (sqP * fP + sqT * fT);
    }

    // block reduction in double for stable sum
    __shared__ double sm[256];
    int tid = threadIdx.x;
    sm[tid] = (double)term;
    __syncthreads();
    for (int s = 128; s > 0; s >>= 1) {
        if (tid < s) sm[tid] += sm[tid + s];
        __syncthreads();
    }
    if (tid == 0) atomicAdd(&g_accum, sm[0]);
}

// ---------------------------------------------------------------------------
// K3: finalize mean
// ---------------------------------------------------------------------------
__global__ void k_final(float* out) {
    out[0] = (float)(g_accum / (double)NPIX);
}

extern "C" void kernel_launch(void* const* d_in, const int* in_sizes, int n_in,
                              void* d_out, int out_size) {
    const float* pred   = (const float*)d_in[0];
    const float* target = (const float*)d_in[1];
    float* out = (float*)d_out;

    k_zero<<<1, 64>>>();
    k_rowpass<<<2 * BB * HH, WW>>>(pred, target);
    k_loss<<<(NPIX + 255) / 256, 256>>>(pred, target);
    k_final<<<1, 1>>>(out);
}

// round 3
// speedup vs baseline: 1.1224x; 1.1224x over previous
#include <cuda_runtime.h>
#include <cuda_bf16.h>

#define BB 16
#define HH 320
#define WW 320
#define NPIX (BB*HH*WW)       // 1,638,400
#define BIGF 1e12f

// Packed row-pass squared distances: (predA, predB, tgtA, tgtB) per pixel.
// class A = EDT(mask)  -> seed where val<=0.5
// class B = EDT(~mask) -> seed where val>0.5
__device__ float4       g_row4[BB * HH * WW];
__device__ unsigned int g_flags[2];    // bit b set => batch b has foreground
__device__ double       g_accum;
__device__ unsigned int g_done;

// ---------------------------------------------------------------------------
// K1: fused row pass (both tensors). One block per (b, y). 320 threads.
// Outward nearest-seed search with early exit (exact for binary seeds).
// ---------------------------------------------------------------------------
__global__ void __launch_bounds__(WW) k_rowpass(const float* __restrict__ pred,
                                                const float* __restrict__ tgt) {
    int blk = blockIdx.x;
    int b = blk / HH;
    int y = blk % HH;

    __shared__ unsigned char mp[WW], mt[WW];
    __shared__ unsigned char wflag[10][2];

    int x = threadIdx.x;
    int idx = (b * HH + y) * WW + x;
    float pv = pred[idx], tv = tgt[idx];
    unsigned char bp = (pv > 0.5f) ? 1 : 0;
    unsigned char bt = (tv > 0.5f) ? 1 : 0;
    mp[x] = bp; mt[x] = bt;
    __syncthreads();

    unsigned balP = __ballot_sync(0xffffffffu, bp);
    unsigned balT = __ballot_sync(0xffffffffu, bt);
    int w = x >> 5;
    if ((x & 31) == 0) { wflag[w][0] = balP ? 1 : 0; wflag[w][1] = balT ? 1 : 0; }

    int dPA = bp ? -1 : 0;
    int dPB = bp ? 0 : -1;
    int dTA = bt ? -1 : 0;
    int dTB = bt ? 0 : -1;
    #pragma unroll 1
    for (int d = 1; d < WW; ++d) {
        if (dPA >= 0 && dPB >= 0 && dTA >= 0 && dTB >= 0) break;
        int jm = x - d, jp = x + d;
        bool vm = (jm >= 0), vp = (jp < WW);
        unsigned char pm = vm ? mp[jm] : 2, pp = vp ? mp[jp] : 2;
        unsigned char tm = vm ? mt[jm] : 2, tp = vp ? mt[jp] : 2;
        if (dPA < 0 && (pm == 0 || pp == 0)) dPA = d;
        if (dPB < 0 && (pm == 1 || pp == 1)) dPB = d;
        if (dTA < 0 && (tm == 0 || tp == 0)) dTA = d;
        if (dTB < 0 && (tm == 1 || tp == 1)) dTB = d;
    }
    float4 g;
    g.x = (dPA >= 0) ? (float)(dPA * dPA) : BIGF;
    g.y = (dPB >= 0) ? (float)(dPB * dPB) : BIGF;
    g.z = (dTA >= 0) ? (float)(dTA * dTA) : BIGF;
    g.w = (dTB >= 0) ? (float)(dTB * dTB) : BIGF;
    g_row4[idx] = g;

    __syncthreads();
    if (x == 0) {
        int aP = 0, aT = 0;
        #pragma unroll
        for (int i = 0; i < 10; ++i) { aP |= wflag[i][0]; aT |= wflag[i][1]; }
        if (aP) atomicOr(&g_flags[0], 1u << b);
        if (aT) atomicOr(&g_flags[1], 1u << b);
    }
}

// ---------------------------------------------------------------------------
// K2: column pass (bounded exact min-plus on float4) + loss + reduction +
//     finalize (last block writes out and resets state for next replay).
// One block per (b, i). 320 threads (x).
// ---------------------------------------------------------------------------
__global__ void __launch_bounds__(WW) k_loss(const float* __restrict__ pred,
                                             const float* __restrict__ tgt,
                                             float* __restrict__ out) {
    int b = blockIdx.x / HH;
    int i = blockIdx.x % HH;
    int x = threadIdx.x;

    const float4* __restrict__ col = &g_row4[b * HH * WW];

    float4 ub = __ldg(&col[i * WW + x]);
    float mx = fmaxf(fmaxf(ub.x, ub.y), fmaxf(ub.z, ub.w));

    #pragma unroll 1
    for (int d = 1; d < HH; ++d) {
        float dd = (float)(d * d);
        if (dd >= mx) break;
        int jm = i - d, jp = i + d;
        if (jm >= 0) {
            float4 v = __ldg(&col[jm * WW + x]);
            ub.x = fminf(ub.x, v.x + dd);
            ub.y = fminf(ub.y, v.y + dd);
            ub.z = fminf(ub.z, v.z + dd);
            ub.w = fminf(ub.w, v.w + dd);
        }
        if (jp < HH) {
            float4 v = __ldg(&col[jp * WW + x]);
            ub.x = fminf(ub.x, v.x + dd);
            ub.y = fminf(ub.y, v.y + dd);
            ub.z = fminf(ub.z, v.z + dd);
            ub.w = fminf(ub.w, v.w + dd);
        }
        mx = fmaxf(fmaxf(ub.x, ub.y), fmaxf(ub.z, ub.w));
    }
    ub.x = fminf(ub.x, BIGF);
    ub.y = fminf(ub.y, BIGF);
    ub.z = fminf(ub.z, BIGF);
    ub.w = fminf(ub.w, BIGF);

    unsigned fl0 = g_flags[0], fl1 = g_flags[1];
    float fP = (fl0 >> b) & 1u ? 1.0f : 0.0f;
    float fT = (fl1 >> b) & 1u ? 1.0f : 0.0f;

    int idx = (b * HH + i) * WW + x;
    float dv = pred[idx] - tgt[idx];
    double term = (double)(dv * dv * (fP * (ub.x + ub.y) + fT * (ub.z + ub.w)));

    // warp shuffle reduce (doubles), then across 10 warps in shared
    #pragma unroll
    for (int s = 16; s > 0; s >>= 1)
        term += __shfl_down_sync(0xffffffffu, term, s);

    __shared__ double wsum[10];
    int w = x >> 5;
    if ((x & 31) == 0) wsum[w] = term;
    __syncthreads();

    if (x == 0) {
        double s = 0.0;
        #pragma unroll
        for (int k = 0; k < 10; ++k) s += wsum[k];
        atomicAdd(&g_accum, s);
        __threadfence();
        unsigned ticket = atomicAdd(&g_done, 1u);
        if (ticket == gridDim.x - 1) {
            double tot = g_accum;
            out[0] = (float)(tot / (double)NPIX);
            // reset state for next graph replay (deterministic epilogue)
            g_accum = 0.0;
            g_flags[0] = 0u;
            g_flags[1] = 0u;
            __threadfence();
            g_done = 0u;
        }
    }
}

extern "C" void kernel_launch(void* const* d_in, const int* in_sizes, int n_in,
                              void* d_out, int out_size) {
    const float* pred = (const float*)d_in[0];
    const float* tgt  = (const float*)d_in[1];
    float* out = (float*)d_out;

    k_rowpass<<<BB * HH, WW>>>(pred, tgt);
    k_loss<<<BB * HH, WW>>>(pred, tgt, out);
}